// round 7
// baseline (speedup 1.0000x reference)
#include <cuda_runtime.h>
#include <cuda_fp16.h>

// ---------------------------------------------------------------------------
// 2-layer GATConv on GB300 — round 7.
// R6 structure (dst-CSR + warp-per-node gather aggregation, zero scatter
// atomics) with fp16 storage for the gathered feature tables (xl1, h2):
// halves the dominant per-edge L2 gather traffic. All math stays fp32.
// ---------------------------------------------------------------------------

#define NN 100000
#define EE 1600000

static __device__ __align__(16) __half2 g_xl1h[NN * 32];  // layer-1 features, fp16
static __device__ __align__(16) float g_as1[NN * 8];
static __device__ __align__(16) float g_ad1[NN * 8];
static __device__ __align__(16) float g_out1[NN * 64];    // normalized layer-1 output
static __device__ __align__(16) __half2 g_h2h[NN * 20];   // layer-2 features, fp16
static __device__ __align__(16) float g_as2[NN];
static __device__ __align__(16) float g_ad2[NN];
static __device__ int g_cnt[NN];
static __device__ int g_off[NN];
static __device__ int g_pos[NN];
static __device__ int g_bsum[512];
static __device__ int g_esrc[EE];

__device__ __forceinline__ float lrelu(float a) { return a > 0.f ? a : 0.2f * a; }

// ---------------------------------------------------------------------------
// Sort kernels (unchanged from R6)
// ---------------------------------------------------------------------------
__global__ void k_zero(int N) {
    int i = blockIdx.x * blockDim.x + threadIdx.x;
    if (i < N) g_cnt[i] = 0;
}

__global__ void k_hist(const int* __restrict__ dp, int E) {
    int e = blockIdx.x * blockDim.x + threadIdx.x;
    if (e < E) atomicAdd(&g_cnt[dp[e]], 1);
}

__global__ void k_scan1(int N) {
    __shared__ int sm[256];
    int tid = threadIdx.x;
    int i = blockIdx.x * 256 + tid;
    int c = (i < N) ? g_cnt[i] : 0;
    sm[tid] = c;
    __syncthreads();
#pragma unroll
    for (int off = 1; off < 256; off <<= 1) {
        int v = (tid >= off) ? sm[tid - off] : 0;
        __syncthreads();
        sm[tid] += v;
        __syncthreads();
    }
    if (i < N) g_off[i] = sm[tid] - c;
    if (tid == 255) g_bsum[blockIdx.x] = sm[tid];
}

__global__ void k_scan2(int nb) {
    __shared__ int sm[512];
    int tid = threadIdx.x;
    int v = (tid < nb) ? g_bsum[tid] : 0;
    sm[tid] = v;
    __syncthreads();
#pragma unroll
    for (int off = 1; off < 512; off <<= 1) {
        int u = (tid >= off) ? sm[tid - off] : 0;
        __syncthreads();
        sm[tid] += u;
        __syncthreads();
    }
    if (tid < nb) g_bsum[tid] = sm[tid] - v;
}

__global__ void k_scan3(int N) {
    int i = blockIdx.x * blockDim.x + threadIdx.x;
    if (i < N) {
        int o = g_off[i] + g_bsum[i >> 8];
        g_off[i] = o;
        g_pos[i] = o;
    }
}

__global__ void k_scatter(const int* __restrict__ sp, const int* __restrict__ dp, int E) {
    int e = blockIdx.x * blockDim.x + threadIdx.x;
    if (e < E) {
        int p = atomicAdd(&g_pos[dp[e]], 1);
        g_esrc[p] = sp[e];
    }
}

// ---------------------------------------------------------------------------
// K-gemm1: xl1 = x @ W1 [N,64] (stored fp16) + per-head fp32 logits.
// ---------------------------------------------------------------------------
__global__ void k_gemm1(const float* __restrict__ x, const float* __restrict__ W1,
                        const float* __restrict__ a_s, const float* __restrict__ a_d, int N) {
    extern __shared__ float smem[];
    float* sW = smem;               // [128][64]
    float* sx = smem + 128 * 64;    // [64][132] padded

    const int tid = threadIdx.x;
    const int tc = tid & 15;
    const int tr = tid >> 4;

    for (int t = tid; t < 128 * 64; t += 256) sW[t] = W1[t];

    const int row0 = blockIdx.x * 64;
    for (int t = tid; t < 64 * 32; t += 256) {
        int r = t >> 5, kq = t & 31;
        int row = row0 + r;
        float4 v = (row < N) ? *(const float4*)(x + (size_t)row * 128 + kq * 4)
                             : make_float4(0.f, 0.f, 0.f, 0.f);
        float* p = sx + r * 132 + kq * 4;
        p[0] = v.x; p[1] = v.y; p[2] = v.z; p[3] = v.w;
    }
    __syncthreads();

    float acc[4][4];
#pragma unroll
    for (int i = 0; i < 4; i++)
#pragma unroll
        for (int j = 0; j < 4; j++) acc[i][j] = 0.f;

#pragma unroll 4
    for (int k = 0; k < 128; k++) {
        float4 w = *(const float4*)(sW + k * 64 + tc * 4);
#pragma unroll
        for (int i = 0; i < 4; i++) {
            float xv = sx[(tr * 4 + i) * 132 + k];
            acc[i][0] += xv * w.x; acc[i][1] += xv * w.y;
            acc[i][2] += xv * w.z; acc[i][3] += xv * w.w;
        }
    }

    float avs0 = a_s[tc * 4 + 0], avs1 = a_s[tc * 4 + 1], avs2 = a_s[tc * 4 + 2], avs3 = a_s[tc * 4 + 3];
    float avd0 = a_d[tc * 4 + 0], avd1 = a_d[tc * 4 + 1], avd2 = a_d[tc * 4 + 2], avd3 = a_d[tc * 4 + 3];

#pragma unroll
    for (int i = 0; i < 4; i++) {
        int row = row0 + tr * 4 + i;
        if (row < N) {
            g_xl1h[row * 32 + tc * 2]     = __float22half2_rn(make_float2(acc[i][0], acc[i][1]));
            g_xl1h[row * 32 + tc * 2 + 1] = __float22half2_rn(make_float2(acc[i][2], acc[i][3]));
        }
        float ps = acc[i][0] * avs0 + acc[i][1] * avs1 + acc[i][2] * avs2 + acc[i][3] * avs3;
        float pd = acc[i][0] * avd0 + acc[i][1] * avd1 + acc[i][2] * avd2 + acc[i][3] * avd3;
        ps += __shfl_xor_sync(0xffffffff, ps, 1);
        pd += __shfl_xor_sync(0xffffffff, pd, 1);
        if (row < N && (tc & 1) == 0) {
            g_as1[row * 8 + (tc >> 1)] = ps;
            g_ad1[row * 8 + (tc >> 1)] = pd;
        }
    }
}

// ---------------------------------------------------------------------------
// K-agg1: warp per dst node; fp16 row gathers, fp32 accumulation.
// Lane owns cols 2*lane, 2*lane+1 (one half2); head = lane>>2.
// ---------------------------------------------------------------------------
__global__ void __launch_bounds__(256) k_agg1(int N) {
    int w = (blockIdx.x * blockDim.x + threadIdx.x) >> 5;
    int lane = threadIdx.x & 31;
    if (w >= N) return;
    const int d = w;
    const int h = lane >> 2;

    const float adv = g_ad1[d * 8 + h];

    // self loop
    float ea = __expf(lrelu(g_as1[d * 8 + h] + adv));
    float2 v = __half22float2(g_xl1h[d * 32 + lane]);
    float a0 = ea * v.x, a1 = ea * v.y, dsum = ea;

    const int start = g_off[d];
    const int end = start + g_cnt[d];
#pragma unroll 4
    for (int i = start; i < end; i++) {
        int s = g_esrc[i];
        float e2 = __expf(lrelu(g_as1[s * 8 + h] + adv));
        float2 vv = __half22float2(g_xl1h[s * 32 + lane]);
        a0 += e2 * vv.x; a1 += e2 * vv.y; dsum += e2;
    }
    float inv = 1.f / (dsum + 1e-16f);
    *(float2*)(g_out1 + (size_t)d * 64 + lane * 2) = make_float2(a0 * inv, a1 * inv);
}

// ---------------------------------------------------------------------------
// K-gemm2: h2 = elu(out1 + b1) @ W2 [N,40] (stored fp16) + fused logits.
// ---------------------------------------------------------------------------
__global__ void k_gemm2(const float* __restrict__ W2, const float* __restrict__ b1v,
                        const float* __restrict__ asv, const float* __restrict__ adv, int N) {
    __shared__ float sW[64 * 40];
    __shared__ float sx[64 * 66];
    __shared__ float sred[128];
    const int tid = threadIdx.x;

    for (int t = tid; t < 64 * 40; t += 160) sW[t] = W2[t];
    for (int t = tid; t < 128; t += 160) sred[t] = 0.f;

    const int row0 = blockIdx.x * 64;
    for (int t = tid; t < 64 * 16; t += 160) {
        int r = t >> 4, kq = t & 15;
        int row = row0 + r;
        float4 v = (row < N) ? *(const float4*)(g_out1 + (size_t)row * 64 + kq * 4)
                             : make_float4(0.f, 0.f, 0.f, 0.f);
        v.x += b1v[kq * 4 + 0]; v.y += b1v[kq * 4 + 1];
        v.z += b1v[kq * 4 + 2]; v.w += b1v[kq * 4 + 3];
        v.x = v.x > 0.f ? v.x : expm1f(v.x);
        v.y = v.y > 0.f ? v.y : expm1f(v.y);
        v.z = v.z > 0.f ? v.z : expm1f(v.z);
        v.w = v.w > 0.f ? v.w : expm1f(v.w);
        float* p = sx + r * 66 + kq * 4;
        p[0] = v.x; p[1] = v.y; p[2] = v.z; p[3] = v.w;
    }
    __syncthreads();

    const int tc = tid % 10, tr = tid / 10;
    float acc[4][4];
#pragma unroll
    for (int i = 0; i < 4; i++)
#pragma unroll
        for (int j = 0; j < 4; j++) acc[i][j] = 0.f;

#pragma unroll 4
    for (int k = 0; k < 64; k++) {
        float4 w = *(const float4*)(sW + k * 40 + tc * 4);
#pragma unroll
        for (int i = 0; i < 4; i++) {
            float xv = sx[(tr * 4 + i) * 66 + k];
            acc[i][0] += xv * w.x; acc[i][1] += xv * w.y;
            acc[i][2] += xv * w.z; acc[i][3] += xv * w.w;
        }
    }

    float av_s[4], av_d[4];
#pragma unroll
    for (int j = 0; j < 4; j++) { av_s[j] = asv[tc * 4 + j]; av_d[j] = adv[tc * 4 + j]; }

#pragma unroll
    for (int i = 0; i < 4; i++) {
        int r = tr * 4 + i;
        int row = row0 + r;
        if (row < N) {
            g_h2h[row * 20 + tc * 2]     = __float22half2_rn(make_float2(acc[i][0], acc[i][1]));
            g_h2h[row * 20 + tc * 2 + 1] = __float22half2_rn(make_float2(acc[i][2], acc[i][3]));
            float ss = 0.f, sd = 0.f;
#pragma unroll
            for (int j = 0; j < 4; j++) { ss += acc[i][j] * av_s[j]; sd += acc[i][j] * av_d[j]; }
            atomicAdd(&sred[r], ss);
            atomicAdd(&sred[64 + r], sd);
        }
    }
    __syncthreads();
    for (int t = tid; t < 64; t += 160) {
        int row = row0 + t;
        if (row < N) { g_as2[row] = sred[t]; g_ad2[row] = sred[64 + t]; }
    }
}

// ---------------------------------------------------------------------------
// K-agg2: warp per dst node, 40 cols (fp16 gathers). Writes FINAL output.
// Lanes 0..19 own one half2 each; all lanes help with the denominator.
// ---------------------------------------------------------------------------
__global__ void __launch_bounds__(256) k_agg2(float* __restrict__ out,
                                              const float* __restrict__ b2, int N) {
    int w = (blockIdx.x * blockDim.x + threadIdx.x) >> 5;
    int lane = threadIdx.x & 31;
    if (w >= N) return;
    const int d = w;
    const bool act = lane < 20;

    const float adv = g_ad2[d];

    float ea = __expf(lrelu(g_as2[d] + adv));
    float a0 = 0.f, a1 = 0.f, dsum = ea;
    if (act) {
        float2 v = __half22float2(g_h2h[d * 20 + lane]);
        a0 = ea * v.x; a1 = ea * v.y;
    }

    const int start = g_off[d];
    const int end = start + g_cnt[d];
#pragma unroll 4
    for (int i = start; i < end; i++) {
        int s = g_esrc[i];
        float e2 = __expf(lrelu(g_as2[s] + adv));
        dsum += e2;
        if (act) {
            float2 vv = __half22float2(g_h2h[s * 20 + lane]);
            a0 += e2 * vv.x; a1 += e2 * vv.y;
        }
    }
    if (act) {
        float inv = 1.f / (dsum + 1e-16f);
        float2 bv = *(const float2*)(b2 + lane * 2);
        *(float2*)(out + (size_t)d * 40 + lane * 2) =
            make_float2(a0 * inv + bv.x, a1 * inv + bv.y);
    }
}

// ---------------------------------------------------------------------------
extern "C" void kernel_launch(void* const* d_in, const int* in_sizes, int n_in,
                              void* d_out, int out_size) {
    const float* x = (const float*)d_in[0];
    const int* ei = (const int*)d_in[1];   // int32 (JAX x64-disabled downcast)
    const float* W1 = (const float*)d_in[2];
    const float* a_src1 = (const float*)d_in[3];
    const float* a_dst1 = (const float*)d_in[4];
    const float* b1 = (const float*)d_in[5];
    const float* W2 = (const float*)d_in[6];
    const float* a_src2 = (const float*)d_in[7];
    const float* a_dst2 = (const float*)d_in[8];
    const float* b2 = (const float*)d_in[9];
    float* out = (float*)d_out;

    const int N = in_sizes[0] / 128;
    const int E = in_sizes[1] / 2;
    const int* src = ei;
    const int* dst = ei + E;
    const int nb = (N + 255) / 256;

    static const int GEMM1_SMEM = (128 * 64 + 64 * 132) * (int)sizeof(float);
    cudaFuncSetAttribute(k_gemm1, cudaFuncAttributeMaxDynamicSharedMemorySize, GEMM1_SMEM);

    // build dst-sorted CSR
    k_zero<<<nb, 256>>>(N);
    k_hist<<<(E + 255) / 256, 256>>>(dst, E);
    k_scan1<<<nb, 256>>>(N);
    k_scan2<<<1, 512>>>(nb);
    k_scan3<<<nb, 256>>>(N);
    k_scatter<<<(E + 255) / 256, 256>>>(src, dst, E);

    // layer 1
    k_gemm1<<<(N + 63) / 64, 256, GEMM1_SMEM>>>(x, W1, a_src1, a_dst1, N);
    k_agg1<<<(N * 32 + 255) / 256, 256>>>(N);

    // layer 2
    k_gemm2<<<(N + 63) / 64, 160>>>(W2, b1, a_src2, a_dst2, N);
    k_agg2<<<(N * 32 + 255) / 256, 256>>>(out, b2, N);
}

// round 8
// speedup vs baseline: 1.1579x; 1.1579x over previous
#include <cuda_runtime.h>
#include <cuda_fp16.h>

// ---------------------------------------------------------------------------
// 2-layer GATConv on GB300 — round 8.
// R6 structure (dst-CSR + warp-per-node gather aggregation, fp32 tables).
// NEW: gemm1 uses tensor cores (mma.sync.m16n8k16, fp16 in / fp32 acc),
// with per-head logits reduced in-register from the MMA fragments.
// Launch order puts gemm1 4th so ncu (which captures the 4th launch) shows it.
// ---------------------------------------------------------------------------

#define NN 100000
#define EE 1600000

static __device__ __align__(16) float g_xl1[NN * 64];
static __device__ __align__(16) float g_as1[NN * 8];
static __device__ __align__(16) float g_ad1[NN * 8];
static __device__ __align__(16) float g_out1[NN * 64];
static __device__ __align__(16) float g_h2[NN * 40];
static __device__ __align__(16) float g_as2[NN];
static __device__ __align__(16) float g_ad2[NN];
static __device__ int g_cnt[NN];
static __device__ int g_off[NN];
static __device__ int g_pos[NN];
static __device__ int g_bsum[512];
static __device__ int g_esrc[EE];

__device__ __forceinline__ float lrelu(float a) { return a > 0.f ? a : 0.2f * a; }

// ---------------------------------------------------------------------------
// Sort kernels (unchanged from R6)
// ---------------------------------------------------------------------------
__global__ void k_zero(int N) {
    int i = blockIdx.x * blockDim.x + threadIdx.x;
    if (i < N) g_cnt[i] = 0;
}

__global__ void k_hist(const int* __restrict__ dp, int E) {
    int e = blockIdx.x * blockDim.x + threadIdx.x;
    if (e < E) atomicAdd(&g_cnt[dp[e]], 1);
}

__global__ void k_scan1(int N) {
    __shared__ int sm[256];
    int tid = threadIdx.x;
    int i = blockIdx.x * 256 + tid;
    int c = (i < N) ? g_cnt[i] : 0;
    sm[tid] = c;
    __syncthreads();
#pragma unroll
    for (int off = 1; off < 256; off <<= 1) {
        int v = (tid >= off) ? sm[tid - off] : 0;
        __syncthreads();
        sm[tid] += v;
        __syncthreads();
    }
    if (i < N) g_off[i] = sm[tid] - c;
    if (tid == 255) g_bsum[blockIdx.x] = sm[tid];
}

__global__ void k_scan2(int nb) {
    __shared__ int sm[512];
    int tid = threadIdx.x;
    int v = (tid < nb) ? g_bsum[tid] : 0;
    sm[tid] = v;
    __syncthreads();
#pragma unroll
    for (int off = 1; off < 512; off <<= 1) {
        int u = (tid >= off) ? sm[tid - off] : 0;
        __syncthreads();
        sm[tid] += u;
        __syncthreads();
    }
    if (tid < nb) g_bsum[tid] = sm[tid] - v;
}

__global__ void k_scan3(int N) {
    int i = blockIdx.x * blockDim.x + threadIdx.x;
    if (i < N) {
        int o = g_off[i] + g_bsum[i >> 8];
        g_off[i] = o;
        g_pos[i] = o;
    }
}

__global__ void k_scatter(const int* __restrict__ sp, const int* __restrict__ dp, int E) {
    int e = blockIdx.x * blockDim.x + threadIdx.x;
    if (e < E) {
        int p = atomicAdd(&g_pos[dp[e]], 1);
        g_esrc[p] = sp[e];
    }
}

// ---------------------------------------------------------------------------
// K-gemm1 (HMMA): xl1 = x @ W1 [N,64] + per-head logits.
// Block: 256 thr = 8 warps, tile 128 rows x 64 cols, K=128 staged once.
// Warp w: rows (w&3)*32, cols (w>>2)*32. Per warp 2 m16 x 4 n8 fragments.
// ---------------------------------------------------------------------------
#define SX_STRIDE 136   // halves per row (128 + 8 pad)
#define SW_STRIDE 72    // halves per row (64 + 8 pad)

__global__ void __launch_bounds__(256)
k_gemm1(const float* __restrict__ x, const float* __restrict__ W1,
        const float* __restrict__ a_s, const float* __restrict__ a_d, int N) {
    extern __shared__ __half smemh[];
    __half* sxh = smemh;                    // [128][136]
    __half* sWh = smemh + 128 * SX_STRIDE;  // [128][72]

    const int tid = threadIdx.x;
    const int lane = tid & 31;
    const int wid = tid >> 5;
    const int wr = (wid & 3) * 32;          // warp row offset in tile
    const int wc = (wid >> 2) * 32;         // warp col offset
    const int row0 = blockIdx.x * 128;

    // stage x tile (fp32 -> fp16): 128x128, 64 elems per thread
    for (int t = tid; t < 128 * 32; t += 256) {
        int r = t >> 5, q = t & 31;
        int row = row0 + r;
        float4 v = (row < N) ? *(const float4*)(x + (size_t)row * 128 + q * 4)
                             : make_float4(0.f, 0.f, 0.f, 0.f);
        __half2* p = (__half2*)(sxh + r * SX_STRIDE + q * 4);
        p[0] = __float22half2_rn(make_float2(v.x, v.y));
        p[1] = __float22half2_rn(make_float2(v.z, v.w));
    }
    // stage W1 (fp32 -> fp16): 128x64
    for (int t = tid; t < 128 * 16; t += 256) {
        int r = t >> 4, q = t & 15;
        float4 v = *(const float4*)(W1 + r * 64 + q * 4);
        __half2* p = (__half2*)(sWh + r * SW_STRIDE + q * 4);
        p[0] = __float22half2_rn(make_float2(v.x, v.y));
        p[1] = __float22half2_rn(make_float2(v.z, v.w));
    }
    __syncthreads();

    float c[2][4][4];
#pragma unroll
    for (int mi = 0; mi < 2; mi++)
#pragma unroll
        for (int ni = 0; ni < 4; ni++)
#pragma unroll
            for (int q = 0; q < 4; q++) c[mi][ni][q] = 0.f;

    const int lrow = lane & 15;
    const int lhi = lane >> 4;   // 0/1

#pragma unroll
    for (int kt = 0; kt < 128; kt += 16) {
        unsigned a[2][4], b[2][4];
#pragma unroll
        for (int mi = 0; mi < 2; mi++) {
            unsigned addr = (unsigned)__cvta_generic_to_shared(
                sxh + (wr + mi * 16 + lrow) * SX_STRIDE + kt + lhi * 8);
            asm volatile("ldmatrix.sync.aligned.m8n8.x4.shared.b16 {%0,%1,%2,%3}, [%4];"
                         : "=r"(a[mi][0]), "=r"(a[mi][1]), "=r"(a[mi][2]), "=r"(a[mi][3])
                         : "r"(addr));
        }
#pragma unroll
        for (int bi = 0; bi < 2; bi++) {
            unsigned addr = (unsigned)__cvta_generic_to_shared(
                sWh + (kt + lrow) * SW_STRIDE + wc + bi * 16 + lhi * 8);
            asm volatile("ldmatrix.sync.aligned.m8n8.x4.trans.shared.b16 {%0,%1,%2,%3}, [%4];"
                         : "=r"(b[bi][0]), "=r"(b[bi][1]), "=r"(b[bi][2]), "=r"(b[bi][3])
                         : "r"(addr));
        }
#pragma unroll
        for (int mi = 0; mi < 2; mi++)
#pragma unroll
            for (int ni = 0; ni < 4; ni++) {
                unsigned b0 = b[ni >> 1][(ni & 1) * 2];
                unsigned b1 = b[ni >> 1][(ni & 1) * 2 + 1];
                asm volatile(
                    "mma.sync.aligned.m16n8k16.row.col.f32.f16.f16.f32 "
                    "{%0,%1,%2,%3}, {%4,%5,%6,%7}, {%8,%9}, {%0,%1,%2,%3};"
                    : "+f"(c[mi][ni][0]), "+f"(c[mi][ni][1]),
                      "+f"(c[mi][ni][2]), "+f"(c[mi][ni][3])
                    : "r"(a[mi][0]), "r"(a[mi][1]), "r"(a[mi][2]), "r"(a[mi][3]),
                      "r"(b0), "r"(b1));
            }
    }

    // epilogue: write xl1 + per-head logits (head = wc/8 + ni)
    const int tg = lane & 3;      // thread-in-group
    const int gr = lane >> 2;     // row-in-fragment (0..7)
#pragma unroll
    for (int ni = 0; ni < 4; ni++) {
        int colb = wc + ni * 8 + tg * 2;
        float as0 = a_s[colb], as1v = a_s[colb + 1];
        float ad0 = a_d[colb], ad1v = a_d[colb + 1];
        int head = (wc >> 3) + ni;
#pragma unroll
        for (int mi = 0; mi < 2; mi++) {
#pragma unroll
            for (int half = 0; half < 2; half++) {
                int row = row0 + wr + mi * 16 + gr + half * 8;
                float v0 = c[mi][ni][half * 2], v1 = c[mi][ni][half * 2 + 1];
                if (row < N)
                    *(float2*)(g_xl1 + (size_t)row * 64 + colb) = make_float2(v0, v1);
                float ps = v0 * as0 + v1 * as1v;
                float pd = v0 * ad0 + v1 * ad1v;
                ps += __shfl_xor_sync(0xffffffff, ps, 1);
                pd += __shfl_xor_sync(0xffffffff, pd, 1);
                ps += __shfl_xor_sync(0xffffffff, ps, 2);
                pd += __shfl_xor_sync(0xffffffff, pd, 2);
                if (tg == 0 && row < N) {
                    g_as1[row * 8 + head] = ps;
                    g_ad1[row * 8 + head] = pd;
                }
            }
        }
    }
}

// ---------------------------------------------------------------------------
// K-agg1: warp per dst node (unchanged from R6, fp32 tables).
// ---------------------------------------------------------------------------
__global__ void __launch_bounds__(256) k_agg1(int N) {
    int w = (blockIdx.x * blockDim.x + threadIdx.x) >> 5;
    int lane = threadIdx.x & 31;
    if (w >= N) return;
    const int d = w;
    const int c0 = lane * 2;
    const int h = lane >> 2;

    const float adv = g_ad1[d * 8 + h];

    float ea = __expf(lrelu(g_as1[d * 8 + h] + adv));
    float2 v = *(const float2*)(g_xl1 + (size_t)d * 64 + c0);
    float a0 = ea * v.x, a1 = ea * v.y, dsum = ea;

    const int start = g_off[d];
    const int end = start + g_cnt[d];
#pragma unroll 4
    for (int i = start; i < end; i++) {
        int s = g_esrc[i];
        float e2 = __expf(lrelu(g_as1[s * 8 + h] + adv));
        float2 vv = *(const float2*)(g_xl1 + (size_t)s * 64 + c0);
        a0 += e2 * vv.x; a1 += e2 * vv.y; dsum += e2;
    }
    float inv = 1.f / (dsum + 1e-16f);
    *(float2*)(g_out1 + (size_t)d * 64 + c0) = make_float2(a0 * inv, a1 * inv);
}

// ---------------------------------------------------------------------------
// K-gemm2: h2 = elu(out1 + b1) @ W2 [N,40] + fused logits (R6-proven).
// ---------------------------------------------------------------------------
__global__ void k_gemm2(const float* __restrict__ W2, const float* __restrict__ b1v,
                        const float* __restrict__ asv, const float* __restrict__ adv, int N) {
    __shared__ float sW[64 * 40];
    __shared__ float sx[64 * 66];
    __shared__ float sred[128];
    const int tid = threadIdx.x;

    for (int t = tid; t < 64 * 40; t += 160) sW[t] = W2[t];
    for (int t = tid; t < 128; t += 160) sred[t] = 0.f;

    const int row0 = blockIdx.x * 64;
    for (int t = tid; t < 64 * 16; t += 160) {
        int r = t >> 4, kq = t & 15;
        int row = row0 + r;
        float4 v = (row < N) ? *(const float4*)(g_out1 + (size_t)row * 64 + kq * 4)
                             : make_float4(0.f, 0.f, 0.f, 0.f);
        v.x += b1v[kq * 4 + 0]; v.y += b1v[kq * 4 + 1];
        v.z += b1v[kq * 4 + 2]; v.w += b1v[kq * 4 + 3];
        v.x = v.x > 0.f ? v.x : expm1f(v.x);
        v.y = v.y > 0.f ? v.y : expm1f(v.y);
        v.z = v.z > 0.f ? v.z : expm1f(v.z);
        v.w = v.w > 0.f ? v.w : expm1f(v.w);
        float* p = sx + r * 66 + kq * 4;
        p[0] = v.x; p[1] = v.y; p[2] = v.z; p[3] = v.w;
    }
    __syncthreads();

    const int tc = tid % 10, tr = tid / 10;
    float acc[4][4];
#pragma unroll
    for (int i = 0; i < 4; i++)
#pragma unroll
        for (int j = 0; j < 4; j++) acc[i][j] = 0.f;

#pragma unroll 4
    for (int k = 0; k < 64; k++) {
        float4 w = *(const float4*)(sW + k * 40 + tc * 4);
#pragma unroll
        for (int i = 0; i < 4; i++) {
            float xv = sx[(tr * 4 + i) * 66 + k];
            acc[i][0] += xv * w.x; acc[i][1] += xv * w.y;
            acc[i][2] += xv * w.z; acc[i][3] += xv * w.w;
        }
    }

    float av_s[4], av_d[4];
#pragma unroll
    for (int j = 0; j < 4; j++) { av_s[j] = asv[tc * 4 + j]; av_d[j] = adv[tc * 4 + j]; }

#pragma unroll
    for (int i = 0; i < 4; i++) {
        int r = tr * 4 + i;
        int row = row0 + r;
        if (row < N) {
            *(float4*)(g_h2 + (size_t)row * 40 + tc * 4) =
                make_float4(acc[i][0], acc[i][1], acc[i][2], acc[i][3]);
            float ss = 0.f, sd = 0.f;
#pragma unroll
            for (int j = 0; j < 4; j++) { ss += acc[i][j] * av_s[j]; sd += acc[i][j] * av_d[j]; }
            atomicAdd(&sred[r], ss);
            atomicAdd(&sred[64 + r], sd);
        }
    }
    __syncthreads();
    for (int t = tid; t < 64; t += 160) {
        int row = row0 + t;
        if (row < N) { g_as2[row] = sred[t]; g_ad2[row] = sred[64 + t]; }
    }
}

// ---------------------------------------------------------------------------
// K-agg2: warp per dst node, 40 cols (fp32). Writes FINAL output.
// ---------------------------------------------------------------------------
__global__ void __launch_bounds__(256) k_agg2(float* __restrict__ out,
                                              const float* __restrict__ b2, int N) {
    int w = (blockIdx.x * blockDim.x + threadIdx.x) >> 5;
    int lane = threadIdx.x & 31;
    if (w >= N) return;
    const int d = w;
    const int c0 = lane * 2;
    const bool act = c0 < 40;

    const float adv = g_ad2[d];

    float ea = __expf(lrelu(g_as2[d] + adv));
    float a0 = 0.f, a1 = 0.f, dsum = ea;
    if (act) {
        float2 v = *(const float2*)(g_h2 + (size_t)d * 40 + c0);
        a0 = ea * v.x; a1 = ea * v.y;
    }

    const int start = g_off[d];
    const int end = start + g_cnt[d];
#pragma unroll 4
    for (int i = start; i < end; i++) {
        int s = g_esrc[i];
        float e2 = __expf(lrelu(g_as2[s] + adv));
        dsum += e2;
        if (act) {
            float2 vv = *(const float2*)(g_h2 + (size_t)s * 40 + c0);
            a0 += e2 * vv.x; a1 += e2 * vv.y;
        }
    }
    if (act) {
        float inv = 1.f / (dsum + 1e-16f);
        float2 bv = *(const float2*)(b2 + c0);
        *(float2*)(out + (size_t)d * 40 + c0) =
            make_float2(a0 * inv + bv.x, a1 * inv + bv.y);
    }
}

// ---------------------------------------------------------------------------
extern "C" void kernel_launch(void* const* d_in, const int* in_sizes, int n_in,
                              void* d_out, int out_size) {
    const float* x = (const float*)d_in[0];
    const int* ei = (const int*)d_in[1];   // int32 (JAX x64-disabled downcast)
    const float* W1 = (const float*)d_in[2];
    const float* a_src1 = (const float*)d_in[3];
    const float* a_dst1 = (const float*)d_in[4];
    const float* b1 = (const float*)d_in[5];
    const float* W2 = (const float*)d_in[6];
    const float* a_src2 = (const float*)d_in[7];
    const float* a_dst2 = (const float*)d_in[8];
    const float* b2 = (const float*)d_in[9];
    float* out = (float*)d_out;

    const int N = in_sizes[0] / 128;
    const int E = in_sizes[1] / 2;
    const int* src = ei;
    const int* dst = ei + E;
    const int nb = (N + 255) / 256;

    static const int GEMM1_SMEM = (128 * SX_STRIDE + 128 * SW_STRIDE) * (int)sizeof(__half);
    cudaFuncSetAttribute(k_gemm1, cudaFuncAttributeMaxDynamicSharedMemorySize, GEMM1_SMEM);

    // gemm1 is independent of the CSR build; placed so it is the 4th launch
    // (ncu captures the 4th launch in the stream).
    k_zero<<<nb, 256>>>(N);
    k_hist<<<(E + 255) / 256, 256>>>(dst, E);
    k_scan1<<<nb, 256>>>(N);
    k_gemm1<<<(N + 127) / 128, 256, GEMM1_SMEM>>>(x, W1, a_src1, a_dst1, N);
    k_scan2<<<1, 512>>>(nb);
    k_scan3<<<nb, 256>>>(N);
    k_scatter<<<(E + 255) / 256, 256>>>(src, dst, E);

    k_agg1<<<(N * 32 + 255) / 256, 256>>>(N);
    k_gemm2<<<(N + 63) / 64, 160>>>(W2, b1, a_src2, a_dst2, N);
    k_agg2<<<(N * 32 + 255) / 256, 256>>>(out, b2, N);
}

// round 10
// speedup vs baseline: 1.3194x; 1.1394x over previous
#include <cuda_runtime.h>
#include <cuda_fp16.h>

// ---------------------------------------------------------------------------
// 2-layer GATConv on GB300 — round 10 (R9 with the gemm1 W-staging fix:
// the fp16 W1 tile copy staged only 32 of 64 columns; bounds corrected).
// dst-CSR + warp-per-node gather aggregation (fp32 tables, 2-edge ILP).
// Both GEMMs on tensor cores (mma.sync.m16n8k16 fp16/fp32).
// ---------------------------------------------------------------------------

#define NN 100000
#define EE 1600000

static __device__ __align__(16) float g_xl1[NN * 64];
static __device__ __align__(16) float g_as1[NN * 8];
static __device__ __align__(16) float g_ad1[NN * 8];
static __device__ __align__(16) float g_out1[NN * 64];
static __device__ __align__(16) float g_h2[NN * 40];
static __device__ __align__(16) float g_as2[NN];
static __device__ __align__(16) float g_ad2[NN];
static __device__ __align__(16) __half g_w1h[128 * 64];
static __device__ __align__(16) __half g_w2h[64 * 48];   // padded 40->48, zeros
static __device__ int g_cnt[NN];
static __device__ int g_off[NN];
static __device__ int g_pos[NN];
static __device__ int g_bsum[512];
static __device__ int g_esrc[EE];

__device__ __forceinline__ float lrelu(float a) { return a > 0.f ? a : 0.2f * a; }

// ---------------------------------------------------------------------------
// K-prep: convert W1, W2 to fp16 (W2 padded to 48 cols with zeros).
// ---------------------------------------------------------------------------
__global__ void k_prep(const float* __restrict__ W1, const float* __restrict__ W2) {
    int i = blockIdx.x * 256 + threadIdx.x;
    if (i < 128 * 64) g_w1h[i] = __float2half_rn(W1[i]);
    if (i < 64 * 48) {
        int r = i / 48, c = i - r * 48;
        g_w2h[i] = __float2half_rn(c < 40 ? W2[r * 40 + c] : 0.f);
    }
}

// ---------------------------------------------------------------------------
// Sort kernels
// ---------------------------------------------------------------------------
__global__ void k_zero(int N) {
    int i = blockIdx.x * blockDim.x + threadIdx.x;
    if (i < N) g_cnt[i] = 0;
}

__global__ void k_hist(const int* __restrict__ dp, int E) {
    int e = blockIdx.x * blockDim.x + threadIdx.x;
    if (e < E) atomicAdd(&g_cnt[dp[e]], 1);
}

__global__ void k_scan1(int N) {
    __shared__ int sm[256];
    int tid = threadIdx.x;
    int i = blockIdx.x * 256 + tid;
    int c = (i < N) ? g_cnt[i] : 0;
    sm[tid] = c;
    __syncthreads();
#pragma unroll
    for (int off = 1; off < 256; off <<= 1) {
        int v = (tid >= off) ? sm[tid - off] : 0;
        __syncthreads();
        sm[tid] += v;
        __syncthreads();
    }
    if (i < N) g_off[i] = sm[tid] - c;
    if (tid == 255) g_bsum[blockIdx.x] = sm[tid];
}

__global__ void k_scan2(int nb) {
    __shared__ int sm[512];
    int tid = threadIdx.x;
    int v = (tid < nb) ? g_bsum[tid] : 0;
    sm[tid] = v;
    __syncthreads();
#pragma unroll
    for (int off = 1; off < 512; off <<= 1) {
        int u = (tid >= off) ? sm[tid - off] : 0;
        __syncthreads();
        sm[tid] += u;
        __syncthreads();
    }
    if (tid < nb) g_bsum[tid] = sm[tid] - v;
}

__global__ void k_scan3(int N) {
    int i = blockIdx.x * blockDim.x + threadIdx.x;
    if (i < N) {
        int o = g_off[i] + g_bsum[i >> 8];
        g_off[i] = o;
        g_pos[i] = o;
    }
}

__global__ void k_scatter(const int* __restrict__ sp, const int* __restrict__ dp, int E) {
    int e = blockIdx.x * blockDim.x + threadIdx.x;
    if (e < E) {
        int p = atomicAdd(&g_pos[dp[e]], 1);
        g_esrc[p] = sp[e];
    }
}

// ---------------------------------------------------------------------------
// K-gemm1 (HMMA): xl1 = x @ W1 [N,64] + per-head logits.
// Tile 64 rows x 64 cols, 256 thr = 8 warps: wr=(wid&1)*32, wc=(wid>>1)*16.
// ---------------------------------------------------------------------------
#define SX1 136   // halves per x row (128 + 8)
#define SW1 72    // halves per W row (64 + 8)

__global__ void __launch_bounds__(256)
k_gemm1(const float* __restrict__ x,
        const float* __restrict__ a_s, const float* __restrict__ a_d, int N) {
    __shared__ __half sxh[64 * SX1];
    __shared__ __half sWh[128 * SW1];

    const int tid = threadIdx.x;
    const int lane = tid & 31;
    const int wid = tid >> 5;
    const int wr = (wid & 1) * 32;
    const int wc = (wid >> 1) * 16;
    const int row0 = blockIdx.x * 64;

    // stage x (fp32 -> fp16): 64 x 128
    for (int t = tid; t < 64 * 32; t += 256) {
        int r = t >> 5, q = t & 31;
        int row = row0 + r;
        float4 v = (row < N) ? *(const float4*)(x + (size_t)row * 128 + q * 4)
                             : make_float4(0.f, 0.f, 0.f, 0.f);
        __half2* p = (__half2*)(sxh + r * SX1 + q * 4);
        p[0] = __float22half2_rn(make_float2(v.x, v.y));
        p[1] = __float22half2_rn(make_float2(v.z, v.w));
    }
    // stage W1 fp16: 128 rows x 8 int4 (64 halves) per row  [R9 bug: was 4]
    for (int t = tid; t < 1024; t += 256) {
        int r = t >> 3, q = t & 7;
        *(int4*)(sWh + r * SW1 + q * 8) = *(const int4*)(g_w1h + r * 64 + q * 8);
    }
    __syncthreads();

    float c[2][2][4];
#pragma unroll
    for (int mi = 0; mi < 2; mi++)
#pragma unroll
        for (int ni = 0; ni < 2; ni++)
#pragma unroll
            for (int q = 0; q < 4; q++) c[mi][ni][q] = 0.f;

    const int lrow = lane & 15;
    const int lhi = lane >> 4;

#pragma unroll
    for (int kt = 0; kt < 128; kt += 16) {
        unsigned a[2][4], b[4];
#pragma unroll
        for (int mi = 0; mi < 2; mi++) {
            unsigned addr = (unsigned)__cvta_generic_to_shared(
                sxh + (wr + mi * 16 + lrow) * SX1 + kt + lhi * 8);
            asm volatile("ldmatrix.sync.aligned.m8n8.x4.shared.b16 {%0,%1,%2,%3}, [%4];"
                         : "=r"(a[mi][0]), "=r"(a[mi][1]), "=r"(a[mi][2]), "=r"(a[mi][3])
                         : "r"(addr));
        }
        {
            unsigned addr = (unsigned)__cvta_generic_to_shared(
                sWh + (kt + lrow) * SW1 + wc + lhi * 8);
            asm volatile("ldmatrix.sync.aligned.m8n8.x4.trans.shared.b16 {%0,%1,%2,%3}, [%4];"
                         : "=r"(b[0]), "=r"(b[1]), "=r"(b[2]), "=r"(b[3])
                         : "r"(addr));
        }
#pragma unroll
        for (int mi = 0; mi < 2; mi++)
#pragma unroll
            for (int ni = 0; ni < 2; ni++) {
                asm volatile(
                    "mma.sync.aligned.m16n8k16.row.col.f32.f16.f16.f32 "
                    "{%0,%1,%2,%3}, {%4,%5,%6,%7}, {%8,%9}, {%0,%1,%2,%3};"
                    : "+f"(c[mi][ni][0]), "+f"(c[mi][ni][1]),
                      "+f"(c[mi][ni][2]), "+f"(c[mi][ni][3])
                    : "r"(a[mi][0]), "r"(a[mi][1]), "r"(a[mi][2]), "r"(a[mi][3]),
                      "r"(b[ni * 2]), "r"(b[ni * 2 + 1]));
            }
    }

    const int tg = lane & 3;
    const int gr = lane >> 2;
#pragma unroll
    for (int ni = 0; ni < 2; ni++) {
        int colb = wc + ni * 8 + tg * 2;
        float as0 = a_s[colb], as1v = a_s[colb + 1];
        float ad0 = a_d[colb], ad1v = a_d[colb + 1];
        int head = (wc + ni * 8) >> 3;
#pragma unroll
        for (int mi = 0; mi < 2; mi++) {
#pragma unroll
            for (int half = 0; half < 2; half++) {
                int row = row0 + wr + mi * 16 + gr + half * 8;
                float v0 = c[mi][ni][half * 2], v1 = c[mi][ni][half * 2 + 1];
                if (row < N)
                    *(float2*)(g_xl1 + (size_t)row * 64 + colb) = make_float2(v0, v1);
                float ps = v0 * as0 + v1 * as1v;
                float pd = v0 * ad0 + v1 * ad1v;
                ps += __shfl_xor_sync(0xffffffff, ps, 1);
                pd += __shfl_xor_sync(0xffffffff, pd, 1);
                ps += __shfl_xor_sync(0xffffffff, ps, 2);
                pd += __shfl_xor_sync(0xffffffff, pd, 2);
                if (tg == 0 && row < N) {
                    g_as1[row * 8 + head] = ps;
                    g_ad1[row * 8 + head] = pd;
                }
            }
        }
    }
}

// ---------------------------------------------------------------------------
// K-agg1: warp per dst node; 2-edge ILP.
// ---------------------------------------------------------------------------
__global__ void __launch_bounds__(256) k_agg1(int N) {
    int w = (blockIdx.x * blockDim.x + threadIdx.x) >> 5;
    int lane = threadIdx.x & 31;
    if (w >= N) return;
    const int d = w;
    const int c0 = lane * 2;
    const int h = lane >> 2;

    const float adv = g_ad1[d * 8 + h];

    float ea = __expf(lrelu(g_as1[d * 8 + h] + adv));
    float2 v = *(const float2*)(g_xl1 + (size_t)d * 64 + c0);
    float a0 = ea * v.x, a1 = ea * v.y, dsum = ea;

    const int start = g_off[d];
    const int end = start + g_cnt[d];
    int i = start;
#pragma unroll 2
    for (; i + 1 < end; i += 2) {
        int s0 = g_esrc[i], s1 = g_esrc[i + 1];
        float e0 = __expf(lrelu(g_as1[s0 * 8 + h] + adv));
        float e1 = __expf(lrelu(g_as1[s1 * 8 + h] + adv));
        float2 v0 = *(const float2*)(g_xl1 + (size_t)s0 * 64 + c0);
        float2 v1 = *(const float2*)(g_xl1 + (size_t)s1 * 64 + c0);
        a0 += e0 * v0.x + e1 * v1.x;
        a1 += e0 * v0.y + e1 * v1.y;
        dsum += e0 + e1;
    }
    if (i < end) {
        int s = g_esrc[i];
        float e2 = __expf(lrelu(g_as1[s * 8 + h] + adv));
        float2 vv = *(const float2*)(g_xl1 + (size_t)s * 64 + c0);
        a0 += e2 * vv.x; a1 += e2 * vv.y; dsum += e2;
    }
    float inv = 1.f / (dsum + 1e-16f);
    *(float2*)(g_out1 + (size_t)d * 64 + c0) = make_float2(a0 * inv, a1 * inv);
}

// ---------------------------------------------------------------------------
// K-gemm2 (HMMA): h2 = elu(out1 + b1) @ W2 [N,40(pad48)] + fused logits.
// Tile 128 rows x 48 cols, 256 thr = 8 warps, each warp 16 rows.
// ---------------------------------------------------------------------------
#define SX2 72    // halves per x2 row (64 + 8)
#define SW2 56    // halves per W2 row (48 + 8)

__global__ void __launch_bounds__(256)
k_gemm2(const float* __restrict__ b1v,
        const float* __restrict__ asv, const float* __restrict__ adv, int N) {
    __shared__ __half sxh[128 * SX2];
    __shared__ __half sWh[64 * SW2];

    const int tid = threadIdx.x;
    const int lane = tid & 31;
    const int wid = tid >> 5;
    const int wr = wid * 16;
    const int row0 = blockIdx.x * 128;

    // stage x2 = elu(out1 + b1) -> fp16: 128 x 64
    for (int t = tid; t < 128 * 16; t += 256) {
        int r = t >> 4, q = t & 15;
        int row = row0 + r;
        float4 v = (row < N) ? *(const float4*)(g_out1 + (size_t)row * 64 + q * 4)
                             : make_float4(0.f, 0.f, 0.f, 0.f);
        v.x += b1v[q * 4 + 0]; v.y += b1v[q * 4 + 1];
        v.z += b1v[q * 4 + 2]; v.w += b1v[q * 4 + 3];
        v.x = v.x > 0.f ? v.x : expm1f(v.x);
        v.y = v.y > 0.f ? v.y : expm1f(v.y);
        v.z = v.z > 0.f ? v.z : expm1f(v.z);
        v.w = v.w > 0.f ? v.w : expm1f(v.w);
        __half2* p = (__half2*)(sxh + r * SX2 + q * 4);
        p[0] = __float22half2_rn(make_float2(v.x, v.y));
        p[1] = __float22half2_rn(make_float2(v.z, v.w));
    }
    // stage W2 fp16 padded: 64 rows x 6 int4 (48 halves) per row
    for (int t = tid; t < 384; t += 256) {
        int r = t / 6, q = t - r * 6;
        *(int4*)(sWh + r * SW2 + q * 8) = *(const int4*)(g_w2h + r * 48 + q * 8);
    }
    __syncthreads();

    float c[6][4];
#pragma unroll
    for (int ni = 0; ni < 6; ni++)
#pragma unroll
        for (int q = 0; q < 4; q++) c[ni][q] = 0.f;

    const int lrow = lane & 15;
    const int lhi = lane >> 4;

#pragma unroll
    for (int kt = 0; kt < 64; kt += 16) {
        unsigned a[4], b[3][4];
        {
            unsigned addr = (unsigned)__cvta_generic_to_shared(
                sxh + (wr + lrow) * SX2 + kt + lhi * 8);
            asm volatile("ldmatrix.sync.aligned.m8n8.x4.shared.b16 {%0,%1,%2,%3}, [%4];"
                         : "=r"(a[0]), "=r"(a[1]), "=r"(a[2]), "=r"(a[3])
                         : "r"(addr));
        }
#pragma unroll
        for (int g = 0; g < 3; g++) {
            unsigned addr = (unsigned)__cvta_generic_to_shared(
                sWh + (kt + lrow) * SW2 + g * 16 + lhi * 8);
            asm volatile("ldmatrix.sync.aligned.m8n8.x4.trans.shared.b16 {%0,%1,%2,%3}, [%4];"
                         : "=r"(b[g][0]), "=r"(b[g][1]), "=r"(b[g][2]), "=r"(b[g][3])
                         : "r"(addr));
        }
#pragma unroll
        for (int ni = 0; ni < 6; ni++) {
            asm volatile(
                "mma.sync.aligned.m16n8k16.row.col.f32.f16.f16.f32 "
                "{%0,%1,%2,%3}, {%4,%5,%6,%7}, {%8,%9}, {%0,%1,%2,%3};"
                : "+f"(c[ni][0]), "+f"(c[ni][1]), "+f"(c[ni][2]), "+f"(c[ni][3])
                : "r"(a[0]), "r"(a[1]), "r"(a[2]), "r"(a[3]),
                  "r"(b[ni >> 1][(ni & 1) * 2]), "r"(b[ni >> 1][(ni & 1) * 2 + 1]));
        }
    }

    const int tg = lane & 3;
    const int gr = lane >> 2;
#pragma unroll
    for (int half = 0; half < 2; half++) {
        int row = row0 + wr + gr + half * 8;
        float ps = 0.f, pd = 0.f;
#pragma unroll
        for (int ni = 0; ni < 5; ni++) {
            int colb = ni * 8 + tg * 2;
            float v0 = c[ni][half * 2], v1 = c[ni][half * 2 + 1];
            if (row < N)
                *(float2*)(g_h2 + (size_t)row * 40 + colb) = make_float2(v0, v1);
            ps += v0 * asv[colb] + v1 * asv[colb + 1];
            pd += v0 * adv[colb] + v1 * adv[colb + 1];
        }
        ps += __shfl_xor_sync(0xffffffff, ps, 1);
        pd += __shfl_xor_sync(0xffffffff, pd, 1);
        ps += __shfl_xor_sync(0xffffffff, ps, 2);
        pd += __shfl_xor_sync(0xffffffff, pd, 2);
        if (tg == 0 && row < N) {
            g_as2[row] = ps;
            g_ad2[row] = pd;
        }
    }
}

// ---------------------------------------------------------------------------
// K-agg2: warp per dst node, 40 cols; 2-edge ILP. Writes FINAL output.
// ---------------------------------------------------------------------------
__global__ void __launch_bounds__(256) k_agg2(float* __restrict__ out,
                                              const float* __restrict__ b2, int N) {
    int w = (blockIdx.x * blockDim.x + threadIdx.x) >> 5;
    int lane = threadIdx.x & 31;
    if (w >= N) return;
    const int d = w;
    const int c0 = lane * 2;
    const bool act = c0 < 40;

    const float adv = g_ad2[d];

    float ea = __expf(lrelu(g_as2[d] + adv));
    float a0 = 0.f, a1 = 0.f, dsum = ea;
    if (act) {
        float2 v = *(const float2*)(g_h2 + (size_t)d * 40 + c0);
        a0 = ea * v.x; a1 = ea * v.y;
    }

    const int start = g_off[d];
    const int end = start + g_cnt[d];
    int i = start;
#pragma unroll 2
    for (; i + 1 < end; i += 2) {
        int s0 = g_esrc[i], s1 = g_esrc[i + 1];
        float e0 = __expf(lrelu(g_as2[s0] + adv));
        float e1 = __expf(lrelu(g_as2[s1] + adv));
        dsum += e0 + e1;
        if (act) {
            float2 v0 = *(const float2*)(g_h2 + (size_t)s0 * 40 + c0);
            float2 v1 = *(const float2*)(g_h2 + (size_t)s1 * 40 + c0);
            a0 += e0 * v0.x + e1 * v1.x;
            a1 += e0 * v0.y + e1 * v1.y;
        }
    }
    if (i < end) {
        int s = g_esrc[i];
        float e2 = __expf(lrelu(g_as2[s] + adv));
        dsum += e2;
        if (act) {
            float2 vv = *(const float2*)(g_h2 + (size_t)s * 40 + c0);
            a0 += e2 * vv.x; a1 += e2 * vv.y;
        }
    }
    if (act) {
        float inv = 1.f / (dsum + 1e-16f);
        float2 bv = *(const float2*)(b2 + c0);
        *(float2*)(out + (size_t)d * 40 + c0) =
            make_float2(a0 * inv + bv.x, a1 * inv + bv.y);
    }
}

// ---------------------------------------------------------------------------
extern "C" void kernel_launch(void* const* d_in, const int* in_sizes, int n_in,
                              void* d_out, int out_size) {
    const float* x = (const float*)d_in[0];
    const int* ei = (const int*)d_in[1];   // int32 (JAX x64-disabled downcast)
    const float* W1 = (const float*)d_in[2];
    const float* a_src1 = (const float*)d_in[3];
    const float* a_dst1 = (const float*)d_in[4];
    const float* b1 = (const float*)d_in[5];
    const float* W2 = (const float*)d_in[6];
    const float* a_src2 = (const float*)d_in[7];
    const float* a_dst2 = (const float*)d_in[8];
    const float* b2 = (const float*)d_in[9];
    float* out = (float*)d_out;

    const int N = in_sizes[0] / 128;
    const int E = in_sizes[1] / 2;
    const int* src = ei;
    const int* dst = ei + E;
    const int nb = (N + 255) / 256;

    // order keeps gemm1 as the 4th launch (ncu captures launch #4)
    k_prep<<<32, 256>>>(W1, W2);
    k_zero<<<nb, 256>>>(N);
    k_hist<<<(E + 255) / 256, 256>>>(dst, E);
    k_gemm1<<<(N + 63) / 64, 256>>>(x, a_src1, a_dst1, N);
    k_scan1<<<nb, 256>>>(N);
    k_scan2<<<1, 512>>>(nb);
    k_scan3<<<nb, 256>>>(N);
    k_scatter<<<(E + 255) / 256, 256>>>(src, dst, E);

    k_agg1<<<(N * 32 + 255) / 256, 256>>>(N);
    k_gemm2<<<(N + 127) / 128, 256>>>(b1, a_src2, a_dst2, N);
    k_agg2<<<(N * 32 + 255) / 256, 256>>>(out, b2, N);
}